// round 2
// baseline (speedup 1.0000x reference)
#include <cuda_runtime.h>
#include <cuda_bf16.h>

#define N_NODES 100000
#define N_EDGES 3200000
#define DIM 64

// Scratch (allocation-free rule: __device__ globals)
__device__ float g_ebuf[N_EDGES];    // per-edge exp(leaky_relu(e))
__device__ float g_denom[N_NODES];   // per-node softmax denominator
__device__ float g_ssrc[N_NODES];
__device__ float g_sdst[N_NODES];

// ---------------------------------------------------------------------------
// K0: zero output + denom
__global__ void k_init(float* __restrict__ out) {
    int i = blockIdx.x * blockDim.x + threadIdx.x;
    if (i < N_NODES * DIM) out[i] = 0.0f;
    if (i < N_NODES) g_denom[i] = 0.0f;
}

// ---------------------------------------------------------------------------
// K1: per-node scores. One warp per node; lane l covers dims l and l+32.
__global__ void k_scores(const float* __restrict__ feat,
                         const float* __restrict__ aw) {
    int warp = (blockIdx.x * blockDim.x + threadIdx.x) >> 5;
    int lane = threadIdx.x & 31;
    if (warp >= N_NODES) return;
    float f0 = feat[warp * DIM + lane];
    float f1 = feat[warp * DIM + 32 + lane];
    float ss = f0 * __ldg(&aw[lane])      + f1 * __ldg(&aw[32 + lane]);
    float sd = f0 * __ldg(&aw[64 + lane]) + f1 * __ldg(&aw[96 + lane]);
    #pragma unroll
    for (int o = 16; o > 0; o >>= 1) {
        ss += __shfl_xor_sync(0xFFFFFFFFu, ss, o);
        sd += __shfl_xor_sync(0xFFFFFFFFu, sd, o);
    }
    if (lane == 0) {
        g_ssrc[warp] = ss;
        g_sdst[warp] = sd;
    }
}

// ---------------------------------------------------------------------------
// K2: per-edge: ee = exp(leaky_relu(s_src[src]+s_dst[dst])); denom[dst] += ee
// (segment-max dropped: exp(e)/sum(exp(e)) == exp(e-m)/sum(exp(e-m)); scores
//  are ~N(0,1) so no overflow risk in fp32.)
__global__ void k_edge(const int* __restrict__ src,
                       const int* __restrict__ dst) {
    int i = blockIdx.x * blockDim.x + threadIdx.x;
    if (i >= N_EDGES) return;
    int s = src[i];
    int d = dst[i];
    float e = g_ssrc[s] + g_sdst[d];
    e = (e > 0.0f) ? e : 0.01f * e;
    float ee = expf(e);
    g_ebuf[i] = ee;
    atomicAdd(&g_denom[d], ee);
}

// ---------------------------------------------------------------------------
// K3: scatter: out[dst] += (ee/denom[dst]) * features[src]
// 16 threads per edge, one float4 chunk each -> coalesced 256B row read,
// vector RED (atomicAdd float4, sm_90+) for the accumulate.
__global__ void k_scatter(const float* __restrict__ feat,
                          const int* __restrict__ src,
                          const int* __restrict__ dst,
                          float* __restrict__ out) {
    long long tid = (long long)blockIdx.x * blockDim.x + threadIdx.x;
    int edge = (int)(tid >> 4);
    int c = (int)(tid & 15);
    if (edge >= N_EDGES) return;
    int s = src[edge];
    int d = dst[edge];
    float alpha = g_ebuf[edge] / g_denom[d];
    float4 v = reinterpret_cast<const float4*>(feat + (size_t)s * DIM)[c];
    v.x *= alpha; v.y *= alpha; v.z *= alpha; v.w *= alpha;
    atomicAdd(reinterpret_cast<float4*>(out + (size_t)d * DIM) + c, v);
}

// ---------------------------------------------------------------------------
// K4: in-place ELU
__global__ void k_elu(float* __restrict__ out) {
    int i = blockIdx.x * blockDim.x + threadIdx.x;
    if (i >= N_NODES * DIM) return;
    float x = out[i];
    out[i] = (x > 0.0f) ? x : expm1f(x);
}

// ---------------------------------------------------------------------------
extern "C" void kernel_launch(void* const* d_in, const int* in_sizes, int n_in,
                              void* d_out, int out_size) {
    const float* feat = (const float*)d_in[0];
    const float* aw   = (const float*)d_in[1];
    const int*   src  = (const int*)d_in[2];
    const int*   dst  = (const int*)d_in[3];
    float* out = (float*)d_out;

    const int T = 256;
    k_init<<<(N_NODES * DIM + T - 1) / T, T>>>(out);
    k_scores<<<(N_NODES * 32 + T - 1) / T, T>>>(feat, aw);
    k_edge<<<(N_EDGES + T - 1) / T, T>>>(src, dst);
    long long scatter_threads = (long long)N_EDGES * 16;
    k_scatter<<<(unsigned)((scatter_threads + T - 1) / T), T>>>(feat, src, dst, out);
    k_elu<<<(N_NODES * DIM + T - 1) / T, T>>>(out);
}